// round 13
// baseline (speedup 1.0000x reference)
#include <cuda_runtime.h>
#include <cuda_fp16.h>
#include <math.h>
#include <cstdint>

#define BNUM 4096
#define EDIM 128
#define LHID 128
#define HDIM 64
#define NGATE 512
#define NAB 300
#define NMV 900
#define INDIM 7808

#define NCOL_MV (48 * NGATE)   // 24576
#define NCOL_AB (12 * NGATE)   // 6144
#define MPAD_MV 1024
#define MPAD_AB 384
#define NTILE_MV (NCOL_MV / 128)   // 192
#define MTILE_MV (MPAD_MV / 128)   // 8
#define NTILE_AB (NCOL_AB / 128)   // 48
#define MTILE_AB (MPAD_AB / 128)   // 3
#define CTAS_MV (NTILE_MV * MTILE_MV)   // 1536
#define CTAS_AB (NTILE_AB * MTILE_AB)   // 144
#define SPLIT_BLOCKS (MPAD_MV + MPAD_AB + NCOL_MV + NCOL_AB)

// ---------------- scratch (device globals; no allocation allowed) -------------
__device__ __half g_Tab[NAB * NCOL_AB];        // 3.7 MB fp16
__device__ __half g_Tmv[NMV * NCOL_MV];        // 44.2 MB fp16
__device__ __half g_Amv[MPAD_MV * EDIM];
__device__ __half g_Aab[MPAD_AB * EDIM];
__device__ __half g_Bmv[NCOL_MV * EDIM];       // 6.3 MB
__device__ __half g_Bab[NCOL_AB * EDIM];       // 1.6 MB
__device__ float g_WcombT[84 * NGATE];
__device__ float g_WhhT[LHID * NGATE];
__device__ float g_bias[NGATE];
__device__ float g_Num[BNUM * NGATE];          // bias + numerical@Wcomb^T, 8 MB
__device__ float g_h1[BNUM * LHID];
__device__ float g_c1[BNUM * LHID];

typedef unsigned long long u64;

__device__ __forceinline__ u64 pk2(float x, float y) {
    u64 r;
    asm("mov.b64 %0, {%1, %2};" : "=l"(r) : "r"(__float_as_uint(x)), "r"(__float_as_uint(y)));
    return r;
}
__device__ __forceinline__ void upk2(u64 v, float& x, float& y) {
    unsigned a, b;
    asm("mov.b64 {%0, %1}, %2;" : "=r"(a), "=r"(b) : "l"(v));
    x = __uint_as_float(a); y = __uint_as_float(b);
}
__device__ __forceinline__ void ffma2(u64& d, u64 a, u64 b) {
    asm("fma.rn.f32x2 %0, %1, %2, %0;" : "+l"(d) : "l"(a), "l"(b));
}
__device__ __forceinline__ void fadd2(u64& d, u64 a) {
    asm("add.rn.f32x2 %0, %1, %0;" : "+l"(d) : "l"(a));
}

__device__ __forceinline__ uint32_t smem_to_u32(const void* p) {
    uint32_t a;
    asm("{ .reg .u64 t; cvta.to.shared.u64 t, %1; cvt.u32.u64 %0, t; }" : "=r"(a) : "l"(p));
    return a;
}

__device__ __forceinline__ void ldsm4(uint32_t* r, uint32_t addr) {
    asm volatile("ldmatrix.sync.aligned.m8n8.x4.shared.b16 {%0,%1,%2,%3}, [%4];"
        : "=r"(r[0]), "=r"(r[1]), "=r"(r[2]), "=r"(r[3]) : "r"(addr));
}
__device__ __forceinline__ void mma16816(float* c, const uint32_t* a, uint32_t b0, uint32_t b1) {
    asm volatile("mma.sync.aligned.m16n8k16.row.col.f32.f16.f16.f32 "
        "{%0,%1,%2,%3}, {%4,%5,%6,%7}, {%8,%9}, {%0,%1,%2,%3};"
        : "+f"(c[0]), "+f"(c[1]), "+f"(c[2]), "+f"(c[3])
        : "r"(a[0]), "r"(a[1]), "r"(a[2]), "r"(a[3]), "r"(b0), "r"(b1));
}
__device__ __forceinline__ void cp16(uint32_t dst, const void* src) {
    asm volatile("cp.async.cg.shared.global [%0], [%1], 16;" :: "r"(dst), "l"(src));
}
#define CP_COMMIT() asm volatile("cp.async.commit_group;" ::: "memory")
#define CP_WAIT1()  asm volatile("cp.async.wait_group 1;" ::: "memory")
#define CP_WAIT0()  asm volatile("cp.async.wait_group 0;" ::: "memory")

// add 8 fp16 gates (one uint4) into 4 packed f32-pair accumulators
__device__ __forceinline__ void addh8(u64* acc4, uint4 v) {
    const __half2* h = (const __half2*)&v;
#pragma unroll
    for (int j = 0; j < 4; j++) {
        float lo = __low2float(h[j]), hi = __high2float(h[j]);
        fadd2(acc4[j], pk2(lo, hi));
    }
}

__device__ __forceinline__ float fast_sigmoid(float x) {
    return 1.f / (1.f + __expf(-x));
}
__device__ __forceinline__ float fast_tanh(float x) {
    return 1.f - 2.f / (1.f + __expf(2.f * x));
}

// ---------------- kernel 1: fused split + A2 -----------------------------------
__global__ __launch_bounds__(128) void kernelSplitA2(
    const float* __restrict__ move_emb, const float* __restrict__ ability_emb,
    const float* __restrict__ Wih, const float* __restrict__ num_W,
    const float* __restrict__ num_b, const float* __restrict__ bih,
    const float* __restrict__ bhh, const float* __restrict__ Whh,
    __half* __restrict__ amv, __half* __restrict__ aab,
    __half* __restrict__ bmv, __half* __restrict__ bab)
{
    const int blk = blockIdx.x, k = threadIdx.x;
    if (blk < MPAD_MV + MPAD_AB) {
        int v; const float* emb; int V; __half* out;
        if (blk < MPAD_MV) { v = blk; emb = move_emb; V = NMV; out = amv; }
        else { v = blk - MPAD_MV; emb = ability_emb; V = NAB; out = aab; }
        float x = (v < V) ? emb[v * EDIM + k] : 0.f;
        out[v * EDIM + k] = __float2half_rn(x);
    } else if (blk < SPLIT_BLOCKS) {
        int n = blk - (MPAD_MV + MPAD_AB);
        int colBase; __half* out;
        if (n < NCOL_MV) { colBase = 12 * EDIM; out = bmv; }
        else { n -= NCOL_MV; colBase = 0; out = bab; }
        int s = n >> 9, j = n & 511;
        out[n * EDIM + k] = __float2half_rn(Wih[(size_t)j * INDIM + colBase + s * EDIM + k]);
    } else {
        // A2: fold numerical path + bias; transpose Whh
        const int j = blk - SPLIT_BLOCKS;
        __shared__ float wrow[128];
        const int tid = k;
        wrow[tid] = Wih[(size_t)j * INDIM + 7680 + tid];
        g_WhhT[tid * NGATE + j] = Whh[j * LHID + tid];
        __syncthreads();
        if (tid < 84) {
            float s = 0.f;
            for (int kk = 0; kk < 128; kk++) s += wrow[kk] * num_W[kk * 84 + tid];
            g_WcombT[tid * NGATE + j] = s;
        } else if (tid == 84) {
            float s = bih[j] + bhh[j];
            for (int kk = 0; kk < 128; kk++) s += num_b[kk] * wrow[kk];
            g_bias[j] = s;
        }
    }
}

// ---------------- kernel 2: g_Num = bias + numerical @ Wcomb^T -----------------
__global__ __launch_bounds__(256) void kernelNum(const float* __restrict__ numerical)
{
    extern __shared__ float smn[];
    float* Ns = smn;               // [64][85]
    float* Ws = smn + 64 * 85;     // [84][128]
    const int tid = threadIdx.x;
    const int b0 = blockIdx.x * 64;
    const int j0 = blockIdx.y * 128;

    for (int idx = tid; idx < 64 * 84; idx += 256) {
        int r = idx / 84, t = idx - r * 84;
        Ns[r * 85 + t] = numerical[(b0 + r) * 84 + t];
    }
    for (int idx = tid; idx < 84 * 128; idx += 256) {
        int t = idx >> 7, j = idx & 127;
        Ws[t * 128 + j] = g_WcombT[t * NGATE + j0 + j];
    }
    __syncthreads();

    const int gq = tid & 31;
    const int rg = tid >> 5;
    u64 acc[8][2];
    {
        const ulonglong2 bb = *(const ulonglong2*)&g_bias[j0 + gq * 4];
#pragma unroll
        for (int i = 0; i < 8; i++) { acc[i][0] = bb.x; acc[i][1] = bb.y; }
    }
    for (int t = 0; t < 84; t++) {
        const ulonglong2 w = *(const ulonglong2*)&Ws[t * 128 + gq * 4];
#pragma unroll
        for (int i = 0; i < 8; i++) {
            float nv = Ns[(rg * 8 + i) * 85 + t];
            u64 aa = pk2(nv, nv);
            ffma2(acc[i][0], aa, w.x); ffma2(acc[i][1], aa, w.y);
        }
    }
#pragma unroll
    for (int i = 0; i < 8; i++) {
        ulonglong2 o; o.x = acc[i][0]; o.y = acc[i][1];
        *(ulonglong2*)&g_Num[(size_t)(b0 + rg * 8 + i) * NGATE + j0 + gq * 4] = o;
    }
}

// ---------------- kernel 3: fp16 HMMA GEMM  C[M,N] = A[M,128] @ B[N,128]^T -----
__device__ __forceinline__ uint32_t swzh(int row, int chunk) {
    return (uint32_t)(row * 128 + ((chunk ^ (row & 7)) << 4));
}

__global__ __launch_bounds__(256, 2) void kernelTC(
    const __half* __restrict__ Amv, const __half* __restrict__ Bmv,
    const __half* __restrict__ Aab, const __half* __restrict__ Bab,
    __half* __restrict__ Cmv, __half* __restrict__ Cab)
{
    __shared__ __align__(16) char As[2][16384];
    __shared__ __align__(16) char Bs[2][16384];

    const int cta = blockIdx.x;
    const __half *A, *B;
    __half* C;
    int mrow0, nrow0, Mrows, Ncols;
    if (cta < CTAS_MV) {
        A = Amv; B = Bmv; C = Cmv; Mrows = NMV; Ncols = NCOL_MV;
        mrow0 = (cta % MTILE_MV) * 128;
        nrow0 = (cta / MTILE_MV) * 128;
    } else {
        int c2 = cta - CTAS_MV;
        A = Aab; B = Bab; C = Cab; Mrows = NAB; Ncols = NCOL_AB;
        mrow0 = (c2 % MTILE_AB) * 128;
        nrow0 = (c2 / MTILE_AB) * 128;
    }

    const int tid = threadIdx.x;
    const int warp = tid >> 5, lane = tid & 31;
    const int warp_m = warp >> 2;
    const int warp_n = warp & 3;

    const uint32_t asBase = smem_to_u32(As);
    const uint32_t bsBase = smem_to_u32(Bs);

#pragma unroll
    for (int h = 0; h < 2; h++) {
#pragma unroll
        for (int i = 0; i < 4; i++) {
            int idx = i * 256 + tid;
            int row = idx >> 3, ch = idx & 7;
            cp16(asBase + h * 16384 + swzh(row, ch),
                 A + (size_t)(mrow0 + row) * EDIM + h * 64 + ch * 8);
            cp16(bsBase + h * 16384 + swzh(row, ch),
                 B + (size_t)(nrow0 + row) * EDIM + h * 64 + ch * 8);
        }
        CP_COMMIT();
    }

    float acc[4][4][4];
#pragma unroll
    for (int i = 0; i < 4; i++)
#pragma unroll
        for (int j = 0; j < 4; j++)
#pragma unroll
            for (int q = 0; q < 4; q++) acc[i][j][q] = 0.f;

    const int lrow = lane & 15;
    const int lsel = lane >> 4;

#pragma unroll
    for (int h = 0; h < 2; h++) {
        if (h == 0) { CP_WAIT1(); } else { CP_WAIT0(); }
        __syncthreads();
        const uint32_t ab = asBase + h * 16384;
        const uint32_t bb = bsBase + h * 16384;
#pragma unroll
        for (int ks = 0; ks < 4; ks++) {
            const int chunk = ks * 2 + lsel;
            uint32_t af[4][4], bf[2][4];
#pragma unroll
            for (int mt = 0; mt < 4; mt++)
                ldsm4(af[mt], ab + swzh(warp_m * 64 + mt * 16 + lrow, chunk));
#pragma unroll
            for (int pr = 0; pr < 2; pr++)
                ldsm4(bf[pr], bb + swzh(warp_n * 32 + pr * 16 + lrow, chunk));
#pragma unroll
            for (int mt = 0; mt < 4; mt++)
#pragma unroll
                for (int nt = 0; nt < 4; nt++) {
                    int pr = nt >> 1, hf = nt & 1;
                    mma16816(acc[mt][nt], af[mt], bf[pr][hf], bf[pr][2 + hf]);
                }
        }
    }

    const int erow = lane >> 2, ecol = (lane & 3) * 2;
#pragma unroll
    for (int mt = 0; mt < 4; mt++) {
#pragma unroll
        for (int nt = 0; nt < 4; nt++) {
            int mg = mrow0 + warp_m * 64 + mt * 16 + erow;
            int cg = nrow0 + warp_n * 32 + nt * 8 + ecol;
            if (mg < Mrows)
                *(__half2*)(C + (size_t)mg * Ncols + cg) =
                    __floats2half2_rn(acc[mt][nt][0], acc[mt][nt][1]);
            if (mg + 8 < Mrows)
                *(__half2*)(C + (size_t)(mg + 8) * Ncols + cg) =
                    __floats2half2_rn(acc[mt][nt][2], acc[mt][nt][3]);
        }
    }
}

// ---------------- kernel 4: gather-sum gates + LSTM cell -----------------------
// 4 rows/block, 1024 blocks, 512 thr: each (row, gate-octet) handled by TWO
// thread-halves (30 slots each) -> half the dependent-load chain per thread.
__global__ __launch_bounds__(512, 2) void kernelB(
    const int* __restrict__ ab_ids, const int* __restrict__ mv_ids,
    const float* __restrict__ h0, const float* __restrict__ c0,
    float* __restrict__ h1_dup, float* __restrict__ c1_dup, int dup)
{
    __shared__ float h0_s[4][128];
    __shared__ int   ids_s[4][64];
    __shared__ float gs[2][4][520];
    const int tid = threadIdx.x;
    const int b0 = blockIdx.x * 4;
    const int q = tid & 63;            // gate octet
    const int rg = (tid >> 6) & 3;     // row 0..3
    const int half = tid >> 8;         // 0/1

    int nz = 0;
    {
        float v = h0[b0 * 128 + tid];
        h0_s[tid >> 7][tid & 127] = v;
        nz |= (v != 0.f);
    }
    if (tid < 4 * 12) ids_s[tid / 12][tid % 12] = ab_ids[b0 * 12 + tid];
    if (tid >= 64 && tid < 64 + 4 * 48) {
        int t = tid - 64;
        ids_s[t / 48][12 + t % 48] = mv_ids[b0 * 48 + t];
    }
    const int anyh = __syncthreads_or(nz);

    u64 acc[4];
    if (half == 0) {
        // Num (incl. bias) + 12 ability slots + move slots 0..17
        const ulonglong2* np = (const ulonglong2*)(g_Num + (size_t)(b0 + rg) * NGATE + q * 8);
        acc[0] = np[0].x; acc[1] = np[0].y; acc[2] = np[1].x; acc[3] = np[1].y;
#pragma unroll
        for (int s = 0; s < 12; s++) {
            const uint4 v = *(const uint4*)(g_Tab +
                ((size_t)(ids_s[rg][s] * 12 + s) << 9) + q * 8);
            addh8(acc, v);
        }
#pragma unroll
        for (int s = 0; s < 18; s++) {
            const uint4 v = *(const uint4*)(g_Tmv +
                ((size_t)(ids_s[rg][12 + s] * 48 + s) << 9) + q * 8);
            addh8(acc, v);
        }
    } else {
        // move slots 18..47
        acc[0] = acc[1] = acc[2] = acc[3] = 0ULL;
#pragma unroll
        for (int s = 18; s < 48; s++) {
            const uint4 v = *(const uint4*)(g_Tmv +
                ((size_t)(ids_s[rg][12 + s] * 48 + s) << 9) + q * 8);
            addh8(acc, v);
        }
    }
    if (anyh) {
        // split Whh k-range: half 0 -> k 0..63, half 1 -> k 64..127
        const int k0 = half * 64;
        for (int k = k0; k < k0 + 64; k++) {
            const ulonglong2* wp = (const ulonglong2*)(g_WhhT + k * NGATE + q * 8);
            const ulonglong2 w0 = wp[0], w1 = wp[1];
            float hv = h0_s[rg][k];
            u64 aa = pk2(hv, hv);
            ffma2(acc[0], aa, w0.x); ffma2(acc[1], aa, w0.y);
            ffma2(acc[2], aa, w1.x); ffma2(acc[3], aa, w1.y);
        }
    }
    {
        float x0, x1, x2, x3;
        upk2(acc[0], x0, x1); upk2(acc[1], x2, x3);
        *(float4*)&gs[half][rg][q * 8] = make_float4(x0, x1, x2, x3);
        upk2(acc[2], x0, x1); upk2(acc[3], x2, x3);
        *(float4*)&gs[half][rg][q * 8 + 4] = make_float4(x0, x1, x2, x3);
    }
    __syncthreads();

    // LSTM cell: 512 threads, one (row, h) each
    {
        const int r = tid >> 7, h = tid & 127;
        float iv = gs[0][r][h]       + gs[1][r][h];
        float fv = gs[0][r][128 + h] + gs[1][r][128 + h];
        float gv = gs[0][r][256 + h] + gs[1][r][256 + h];
        float ov = gs[0][r][384 + h] + gs[1][r][384 + h];
        iv = fast_sigmoid(iv);
        fv = fast_sigmoid(fv);
        ov = fast_sigmoid(ov);
        gv = fast_tanh(gv);
        float c0v = c0[(b0 + r) * LHID + h];
        float c1v = fv * c0v + iv * gv;
        float h1v = ov * fast_tanh(c1v);
        g_c1[(b0 + r) * LHID + h] = c1v;
        g_h1[(b0 + r) * LHID + h] = h1v;
        if (dup) {
            c1_dup[(b0 + r) * LHID + h] = c1v;
            h1_dup[(b0 + r) * LHID + h] = h1v;
        }
    }
}

// ---------------- kernel 5: MLP head + masked softmax (32 rows/block) ----------
#define CROWS 32
__global__ __launch_bounds__(256) void kernelC(
    const float* __restrict__ W1, const float* __restrict__ b1,
    const float* __restrict__ W2, const float* __restrict__ b2,
    const float* __restrict__ Wa, const float* __restrict__ ba,
    const float* __restrict__ mask, float* __restrict__ outp)
{
    extern __shared__ float sm[];
    float* W1t = sm;                 // [128][64]
    float* W2t = W1t + 8192;         // [64][128]
    float* Was = W2t + 8192;         // [9][132]
    float* h1s = Was + 9 * 132;      // [32][132]
    float* t1s = h1s + 32 * 132;     // [32][68]
    float* fts = t1s + 32 * 68;      // [32][132]
    float* lgs = fts + 32 * 132;     // [32][12]
    float* b1s = lgs + 32 * 12;      // 64
    float* b2s = b1s + 64;           // 128
    float* bas = b2s + 128;          // 12
    const int tid = threadIdx.x;
    const int b0 = blockIdx.x * CROWS;

    for (int i = tid; i < 64 * 32; i += 256) {
        int j = i >> 5, kq = i & 31;
        float4 v = *(const float4*)(W1 + j * 128 + kq * 4);
        W1t[(kq * 4 + 0) * 64 + j] = v.x;
        W1t[(kq * 4 + 1) * 64 + j] = v.y;
        W1t[(kq * 4 + 2) * 64 + j] = v.z;
        W1t[(kq * 4 + 3) * 64 + j] = v.w;
    }
    for (int i = tid; i < 128 * 16; i += 256) {
        int kk = i >> 4, jq = i & 15;
        float4 v = *(const float4*)(W2 + kk * 64 + jq * 4);
        W2t[(jq * 4 + 0) * 128 + kk] = v.x;
        W2t[(jq * 4 + 1) * 128 + kk] = v.y;
        W2t[(jq * 4 + 2) * 128 + kk] = v.z;
        W2t[(jq * 4 + 3) * 128 + kk] = v.w;
    }
    for (int i = tid; i < 9 * 32; i += 256) {
        int a = i >> 5, kq = i & 31;
        *(float4*)&Was[a * 132 + kq * 4] = *(const float4*)(Wa + a * 128 + kq * 4);
    }
    for (int i = tid; i < 32 * 32; i += 256) {
        int r = i >> 5, kq = i & 31;
        *(float4*)&h1s[r * 132 + kq * 4] = *(const float4*)(g_h1 + (size_t)(b0 + r) * 128 + kq * 4);
    }
    if (tid < 64) b1s[tid] = b1[tid];
    if (tid >= 64 && tid < 192) b2s[tid - 64] = b2[tid - 64];
    if (tid >= 192 && tid < 201) bas[tid - 192] = ba[tid - 192];
    __syncthreads();

    {
        const int jq = tid & 15, rp = tid >> 4;
        const int j0 = jq * 4, r0 = rp * 2;
        float acc0[4], acc1[4];
#pragma unroll
        for (int q = 0; q < 4; q++) { acc0[q] = b1s[j0 + q]; acc1[q] = acc0[q]; }
        for (int k4 = 0; k4 < 128; k4 += 4) {
            float4 a0 = *(const float4*)&h1s[r0 * 132 + k4];
            float4 a1 = *(const float4*)&h1s[(r0 + 1) * 132 + k4];
            const float* a0p = (const float*)&a0;
            const float* a1p = (const float*)&a1;
#pragma unroll
            for (int t = 0; t < 4; t++) {
                float4 w = *(const float4*)&W1t[(k4 + t) * 64 + j0];
                float av0 = a0p[t], av1 = a1p[t];
                acc0[0] = fmaf(av0, w.x, acc0[0]); acc0[1] = fmaf(av0, w.y, acc0[1]);
                acc0[2] = fmaf(av0, w.z, acc0[2]); acc0[3] = fmaf(av0, w.w, acc0[3]);
                acc1[0] = fmaf(av1, w.x, acc1[0]); acc1[1] = fmaf(av1, w.y, acc1[1]);
                acc1[2] = fmaf(av1, w.z, acc1[2]); acc1[3] = fmaf(av1, w.w, acc1[3]);
            }
        }
        *(float4*)&t1s[r0 * 68 + j0] = make_float4(
            fmaxf(acc0[0], 0.f), fmaxf(acc0[1], 0.f), fmaxf(acc0[2], 0.f), fmaxf(acc0[3], 0.f));
        *(float4*)&t1s[(r0 + 1) * 68 + j0] = make_float4(
            fmaxf(acc1[0], 0.f), fmaxf(acc1[1], 0.f), fmaxf(acc1[2], 0.f), fmaxf(acc1[3], 0.f));
    }
    __syncthreads();

    {
        const int jo = tid & 15, rp = tid >> 4;
        const int kk0 = jo * 8, r0 = rp * 2;
        float acc0[8], acc1[8];
#pragma unroll
        for (int q = 0; q < 8; q++) { acc0[q] = b2s[kk0 + q]; acc1[q] = acc0[q]; }
        for (int j4 = 0; j4 < 64; j4 += 4) {
            float4 a0 = *(const float4*)&t1s[r0 * 68 + j4];
            float4 a1 = *(const float4*)&t1s[(r0 + 1) * 68 + j4];
            const float* a0p = (const float*)&a0;
            const float* a1p = (const float*)&a1;
#pragma unroll
            for (int t = 0; t < 4; t++) {
                float4 w0 = *(const float4*)&W2t[(j4 + t) * 128 + kk0];
                float4 w1 = *(const float4*)&W2t[(j4 + t) * 128 + kk0 + 4];
                float av0 = a0p[t], av1 = a1p[t];
                acc0[0] = fmaf(av0, w0.x, acc0[0]); acc0[1] = fmaf(av0, w0.y, acc0[1]);
                acc0[2] = fmaf(av0, w0.z, acc0[2]); acc0[3] = fmaf(av0, w0.w, acc0[3]);
                acc0[4] = fmaf(av0, w1.x, acc0[4]); acc0[5] = fmaf(av0, w1.y, acc0[5]);
                acc0[6] = fmaf(av0, w1.z, acc0[6]); acc0[7] = fmaf(av0, w1.w, acc0[7]);
                acc1[0] = fmaf(av1, w0.x, acc1[0]); acc1[1] = fmaf(av1, w0.y, acc1[1]);
                acc1[2] = fmaf(av1, w0.z, acc1[2]); acc1[3] = fmaf(av1, w0.w, acc1[3]);
                acc1[4] = fmaf(av1, w1.x, acc1[4]); acc1[5] = fmaf(av1, w1.y, acc1[5]);
                acc1[6] = fmaf(av1, w1.z, acc1[6]); acc1[7] = fmaf(av1, w1.w, acc1[7]);
            }
        }
        *(float4*)&fts[r0 * 132 + kk0] = make_float4(acc0[0], acc0[1], acc0[2], acc0[3]);
        *(float4*)&fts[r0 * 132 + kk0 + 4] = make_float4(acc0[4], acc0[5], acc0[6], acc0[7]);
        *(float4*)&fts[(r0 + 1) * 132 + kk0] = make_float4(acc1[0], acc1[1], acc1[2], acc1[3]);
        *(float4*)&fts[(r0 + 1) * 132 + kk0 + 4] = make_float4(acc1[4], acc1[5], acc1[6], acc1[7]);
    }
    __syncthreads();

    for (int idx = tid; idx < CROWS * 9; idx += 256) {
        int r = idx / 9, a = idx - r * 9;
        float s = bas[a];
        for (int k4 = 0; k4 < 128; k4 += 4) {
            float4 f = *(const float4*)&fts[r * 132 + k4];
            float4 w = *(const float4*)&Was[a * 132 + k4];
            s = fmaf(f.x, w.x, s); s = fmaf(f.y, w.y, s);
            s = fmaf(f.z, w.z, s); s = fmaf(f.w, w.w, s);
        }
        lgs[r * 12 + a] = s;
    }
    __syncthreads();

    if (tid < CROWS) {
        int b = b0 + tid;
        float mx = -1e30f;
        for (int a = 0; a < 9; a++) mx = fmaxf(mx, lgs[tid * 12 + a]);
        float e[9]; float se = 0.f;
        for (int a = 0; a < 9; a++) { e[a] = expf(lgs[tid * 12 + a] - mx); se += e[a]; }
        float pm[9]; float ms = 0.f;
        for (int a = 0; a < 9; a++) {
            float p = e[a] / se;
            pm[a] = p * mask[b * 9 + a];
            ms += pm[a];
        }
        for (int a = 0; a < 9; a++)
            outp[b * 9 + a] = (ms > 0.f) ? pm[a] / ms : e[a] / se;
    }
}

// ---------------- host ---------------------------------------------------------
extern "C" void kernel_launch(void* const* d_in, const int* in_sizes, int n_in,
                              void* d_out, int out_size)
{
    const int*   ab_ids    = (const int*)d_in[0];
    const int*   mv_ids    = (const int*)d_in[1];
    const float* numerical = (const float*)d_in[2];
    const float* mask      = (const float*)d_in[3];
    const float* h0        = (const float*)d_in[4];
    const float* c0        = (const float*)d_in[5];
    const float* ability_emb = (const float*)d_in[6];
    const float* move_emb  = (const float*)d_in[7];
    const float* num_W     = (const float*)d_in[8];
    const float* num_b     = (const float*)d_in[9];
    const float* Wih       = (const float*)d_in[10];
    const float* Whh       = (const float*)d_in[11];
    const float* bih       = (const float*)d_in[12];
    const float* bhh       = (const float*)d_in[13];
    const float* W1        = (const float*)d_in[14];
    const float* b1        = (const float*)d_in[15];
    const float* W2        = (const float*)d_in[16];
    const float* b2        = (const float*)d_in[17];
    const float* Wa        = (const float*)d_in[18];
    const float* ba        = (const float*)d_in[19];
    float* outp = (float*)d_out;

    __half *tab = nullptr, *tmv = nullptr;
    __half *amv = nullptr, *aab = nullptr, *bmv = nullptr, *bab = nullptr;
    cudaGetSymbolAddress((void**)&tab, g_Tab);
    cudaGetSymbolAddress((void**)&tmv, g_Tmv);
    cudaGetSymbolAddress((void**)&amv, g_Amv);
    cudaGetSymbolAddress((void**)&aab, g_Aab);
    cudaGetSymbolAddress((void**)&bmv, g_Bmv);
    cudaGetSymbolAddress((void**)&bab, g_Bab);

    const int smN = (64 * 85 + 84 * 128) * 4;   // 64768 B
    const int smC = (8192 + 8192 + 9 * 132 + 32 * 132 + 32 * 68 + 32 * 132 +
                     32 * 12 + 64 + 128 + 12) * 4;   // ~115 KB
    cudaFuncSetAttribute(kernelNum, cudaFuncAttributeMaxDynamicSharedMemorySize, smN);
    cudaFuncSetAttribute(kernelC, cudaFuncAttributeMaxDynamicSharedMemorySize, smC);

    const int full = (out_size >= BNUM * (9 + LHID + LHID));
    float* h1d = full ? (outp + BNUM * 9) : nullptr;
    float* c1d = full ? (outp + BNUM * 9 + BNUM * LHID) : nullptr;

    // 1: fused split + A2
    kernelSplitA2<<<SPLIT_BLOCKS + NGATE, 128>>>(
        move_emb, ability_emb, Wih, num_W, num_b, bih, bhh, Whh, amv, aab, bmv, bab);

    // 2: numerical-path GEMM
    dim3 gNum(BNUM / 64, NGATE / 128);   // (64, 4)
    kernelNum<<<gNum, 256, smN>>>(numerical);

    // 3: table GEMM
    kernelTC<<<CTAS_MV + CTAS_AB, 256>>>(amv, bmv, aab, bab, tmv, tab);

    // 4: gather-sum + LSTM (split-slot, 512 thr)
    kernelB<<<BNUM / 4, 512>>>(ab_ids, mv_ids, h0, c0, h1d, c1d, full);

    // 5: MLP head + softmax (register-tiled)
    kernelC<<<BNUM / CROWS, 256, smC>>>(W1, b1, W2, b2, Wa, ba, mask, outp);
}

// round 14
// speedup vs baseline: 1.0394x; 1.0394x over previous
#include <cuda_runtime.h>
#include <cuda_fp16.h>
#include <math.h>
#include <cstdint>

#define BNUM 4096
#define EDIM 128
#define LHID 128
#define HDIM 64
#define NGATE 512
#define NAB 300
#define NMV 900
#define INDIM 7808

#define NCOL_MV (48 * NGATE)   // 24576
#define NCOL_AB (12 * NGATE)   // 6144
#define MPAD_MV 1024
#define MPAD_AB 384
#define NTILE_MV (NCOL_MV / 128)   // 192
#define MTILE_MV (MPAD_MV / 128)   // 8
#define NTILE_AB (NCOL_AB / 128)   // 48
#define MTILE_AB (MPAD_AB / 128)   // 3
#define CTAS_MV (NTILE_MV * MTILE_MV)   // 1536
#define CTAS_AB (NTILE_AB * MTILE_AB)   // 144
#define CTAS_NUM 256                     // (BNUM/64) x (NGATE/128)
#define SPLIT_BLOCKS (MPAD_MV + MPAD_AB + NCOL_MV + NCOL_AB)

// ---------------- scratch (device globals; no allocation allowed) -------------
__device__ __half g_Tab[NAB * NCOL_AB];        // 3.7 MB fp16
__device__ __half g_Tmv[NMV * NCOL_MV];        // 44.2 MB fp16
__device__ __half g_Amv[MPAD_MV * EDIM];
__device__ __half g_Aab[MPAD_AB * EDIM];
__device__ __half g_Bmv[NCOL_MV * EDIM];       // 6.3 MB
__device__ __half g_Bab[NCOL_AB * EDIM];       // 1.6 MB
__device__ float g_WcombT[84 * NGATE];
__device__ float g_WhhT[LHID * NGATE];
__device__ float g_bias[NGATE];
__device__ float g_Num[BNUM * NGATE];          // bias + numerical@Wcomb^T, 8 MB
__device__ float g_h1[BNUM * LHID];
__device__ float g_c1[BNUM * LHID];

typedef unsigned long long u64;

__device__ __forceinline__ u64 pk2(float x, float y) {
    u64 r;
    asm("mov.b64 %0, {%1, %2};" : "=l"(r) : "r"(__float_as_uint(x)), "r"(__float_as_uint(y)));
    return r;
}
__device__ __forceinline__ void upk2(u64 v, float& x, float& y) {
    unsigned a, b;
    asm("mov.b64 {%0, %1}, %2;" : "=r"(a), "=r"(b) : "l"(v));
    x = __uint_as_float(a); y = __uint_as_float(b);
}
__device__ __forceinline__ void ffma2(u64& d, u64 a, u64 b) {
    asm("fma.rn.f32x2 %0, %1, %2, %0;" : "+l"(d) : "l"(a), "l"(b));
}
__device__ __forceinline__ void fadd2(u64& d, u64 a) {
    asm("add.rn.f32x2 %0, %1, %0;" : "+l"(d) : "l"(a));
}

__device__ __forceinline__ uint32_t smem_to_u32(const void* p) {
    uint32_t a;
    asm("{ .reg .u64 t; cvta.to.shared.u64 t, %1; cvt.u32.u64 %0, t; }" : "=r"(a) : "l"(p));
    return a;
}

__device__ __forceinline__ void ldsm4(uint32_t* r, uint32_t addr) {
    asm volatile("ldmatrix.sync.aligned.m8n8.x4.shared.b16 {%0,%1,%2,%3}, [%4];"
        : "=r"(r[0]), "=r"(r[1]), "=r"(r[2]), "=r"(r[3]) : "r"(addr));
}
__device__ __forceinline__ void mma16816(float* c, const uint32_t* a, uint32_t b0, uint32_t b1) {
    asm volatile("mma.sync.aligned.m16n8k16.row.col.f32.f16.f16.f32 "
        "{%0,%1,%2,%3}, {%4,%5,%6,%7}, {%8,%9}, {%0,%1,%2,%3};"
        : "+f"(c[0]), "+f"(c[1]), "+f"(c[2]), "+f"(c[3])
        : "r"(a[0]), "r"(a[1]), "r"(a[2]), "r"(a[3]), "r"(b0), "r"(b1));
}
__device__ __forceinline__ void cp16(uint32_t dst, const void* src) {
    asm volatile("cp.async.cg.shared.global [%0], [%1], 16;" :: "r"(dst), "l"(src));
}
#define CP_COMMIT() asm volatile("cp.async.commit_group;" ::: "memory")
#define CP_WAIT1()  asm volatile("cp.async.wait_group 1;" ::: "memory")
#define CP_WAIT0()  asm volatile("cp.async.wait_group 0;" ::: "memory")

// add 8 fp16 gates (one uint4) into 4 packed f32-pair accumulators
__device__ __forceinline__ void addh8(u64* acc4, uint4 v) {
    const __half2* h = (const __half2*)&v;
#pragma unroll
    for (int j = 0; j < 4; j++) {
        float lo = __low2float(h[j]), hi = __high2float(h[j]);
        fadd2(acc4[j], pk2(lo, hi));
    }
}

__device__ __forceinline__ float fast_sigmoid(float x) {
    return 1.f / (1.f + __expf(-x));
}
__device__ __forceinline__ float fast_tanh(float x) {
    return 1.f - 2.f / (1.f + __expf(2.f * x));
}

// ---------------- kernel 1: fused split + A2 -----------------------------------
__global__ __launch_bounds__(128) void kernelSplitA2(
    const float* __restrict__ move_emb, const float* __restrict__ ability_emb,
    const float* __restrict__ Wih, const float* __restrict__ num_W,
    const float* __restrict__ num_b, const float* __restrict__ bih,
    const float* __restrict__ bhh, const float* __restrict__ Whh,
    __half* __restrict__ amv, __half* __restrict__ aab,
    __half* __restrict__ bmv, __half* __restrict__ bab)
{
    const int blk = blockIdx.x, k = threadIdx.x;
    if (blk < MPAD_MV + MPAD_AB) {
        int v; const float* emb; int V; __half* out;
        if (blk < MPAD_MV) { v = blk; emb = move_emb; V = NMV; out = amv; }
        else { v = blk - MPAD_MV; emb = ability_emb; V = NAB; out = aab; }
        float x = (v < V) ? emb[v * EDIM + k] : 0.f;
        out[v * EDIM + k] = __float2half_rn(x);
    } else if (blk < SPLIT_BLOCKS) {
        int n = blk - (MPAD_MV + MPAD_AB);
        int colBase; __half* out;
        if (n < NCOL_MV) { colBase = 12 * EDIM; out = bmv; }
        else { n -= NCOL_MV; colBase = 0; out = bab; }
        int s = n >> 9, j = n & 511;
        out[n * EDIM + k] = __float2half_rn(Wih[(size_t)j * INDIM + colBase + s * EDIM + k]);
    } else {
        // A2: fold numerical path + bias; transpose Whh
        const int j = blk - SPLIT_BLOCKS;
        __shared__ float wrow[128];
        const int tid = k;
        wrow[tid] = Wih[(size_t)j * INDIM + 7680 + tid];
        g_WhhT[tid * NGATE + j] = Whh[j * LHID + tid];
        __syncthreads();
        if (tid < 84) {
            float s = 0.f;
            for (int kk = 0; kk < 128; kk++) s += wrow[kk] * num_W[kk * 84 + tid];
            g_WcombT[tid * NGATE + j] = s;
        } else if (tid == 84) {
            float s = bih[j] + bhh[j];
            for (int kk = 0; kk < 128; kk++) s += num_b[kk] * wrow[kk];
            g_bias[j] = s;
        }
    }
}

// ---------------- kernel 2: merged Num + table GEMM -----------------------------
// CTAs [0, CTAS_NUM): g_Num = bias + numerical @ Wcomb^T (FFMA2 path)
// CTAs [CTAS_NUM, ...): fp16 HMMA table GEMM
__device__ __forceinline__ uint32_t swzh(int row, int chunk) {
    return (uint32_t)(row * 128 + ((chunk ^ (row & 7)) << 4));
}

__global__ __launch_bounds__(256, 2) void kernelTCNum(
    const __half* __restrict__ Amv, const __half* __restrict__ Bmv,
    const __half* __restrict__ Aab, const __half* __restrict__ Bab,
    __half* __restrict__ Cmv, __half* __restrict__ Cab,
    const float* __restrict__ numerical)
{
    extern __shared__ __align__(16) char dynsm[];
    const int tid = threadIdx.x;

    if (blockIdx.x < CTAS_NUM) {
        // ------------- Num branch -------------
        float* Ns = (float*)dynsm;               // [64][85]
        float* Ws = Ns + 64 * 85;                // [84][128]
        const int c3 = blockIdx.x;
        const int b0 = (c3 & 63) * 64;
        const int j0 = (c3 >> 6) * 128;

        for (int idx = tid; idx < 64 * 84; idx += 256) {
            int r = idx / 84, t = idx - r * 84;
            Ns[r * 85 + t] = numerical[(b0 + r) * 84 + t];
        }
        for (int idx = tid; idx < 84 * 128; idx += 256) {
            int t = idx >> 7, j = idx & 127;
            Ws[t * 128 + j] = g_WcombT[t * NGATE + j0 + j];
        }
        __syncthreads();

        const int gq = tid & 31;
        const int rg = tid >> 5;
        u64 acc[8][2];
        {
            const ulonglong2 bb = *(const ulonglong2*)&g_bias[j0 + gq * 4];
#pragma unroll
            for (int i = 0; i < 8; i++) { acc[i][0] = bb.x; acc[i][1] = bb.y; }
        }
        for (int t = 0; t < 84; t++) {
            const ulonglong2 w = *(const ulonglong2*)&Ws[t * 128 + gq * 4];
#pragma unroll
            for (int i = 0; i < 8; i++) {
                float nv = Ns[(rg * 8 + i) * 85 + t];
                u64 aa = pk2(nv, nv);
                ffma2(acc[i][0], aa, w.x); ffma2(acc[i][1], aa, w.y);
            }
        }
#pragma unroll
        for (int i = 0; i < 8; i++) {
            ulonglong2 o; o.x = acc[i][0]; o.y = acc[i][1];
            *(ulonglong2*)&g_Num[(size_t)(b0 + rg * 8 + i) * NGATE + j0 + gq * 4] = o;
        }
        return;
    }

    // ------------- TC branch -------------
    char* As = dynsm;                 // [2][16384]
    char* Bs = dynsm + 32768;         // [2][16384]

    const int cta = blockIdx.x - CTAS_NUM;
    const __half *A, *B;
    __half* C;
    int mrow0, nrow0, Mrows, Ncols;
    if (cta < CTAS_MV) {
        A = Amv; B = Bmv; C = Cmv; Mrows = NMV; Ncols = NCOL_MV;
        mrow0 = (cta % MTILE_MV) * 128;
        nrow0 = (cta / MTILE_MV) * 128;
    } else {
        int c2 = cta - CTAS_MV;
        A = Aab; B = Bab; C = Cab; Mrows = NAB; Ncols = NCOL_AB;
        mrow0 = (c2 % MTILE_AB) * 128;
        nrow0 = (c2 / MTILE_AB) * 128;
    }

    const int warp = tid >> 5, lane = tid & 31;
    const int warp_m = warp >> 2;
    const int warp_n = warp & 3;

    const uint32_t asBase = smem_to_u32(As);
    const uint32_t bsBase = smem_to_u32(Bs);

#pragma unroll
    for (int h = 0; h < 2; h++) {
#pragma unroll
        for (int i = 0; i < 4; i++) {
            int idx = i * 256 + tid;
            int row = idx >> 3, ch = idx & 7;
            cp16(asBase + h * 16384 + swzh(row, ch),
                 A + (size_t)(mrow0 + row) * EDIM + h * 64 + ch * 8);
            cp16(bsBase + h * 16384 + swzh(row, ch),
                 B + (size_t)(nrow0 + row) * EDIM + h * 64 + ch * 8);
        }
        CP_COMMIT();
    }

    float acc[4][4][4];
#pragma unroll
    for (int i = 0; i < 4; i++)
#pragma unroll
        for (int j = 0; j < 4; j++)
#pragma unroll
            for (int q = 0; q < 4; q++) acc[i][j][q] = 0.f;

    const int lrow = lane & 15;
    const int lsel = lane >> 4;

#pragma unroll
    for (int h = 0; h < 2; h++) {
        if (h == 0) { CP_WAIT1(); } else { CP_WAIT0(); }
        __syncthreads();
        const uint32_t ab = asBase + h * 16384;
        const uint32_t bb = bsBase + h * 16384;
#pragma unroll
        for (int ks = 0; ks < 4; ks++) {
            const int chunk = ks * 2 + lsel;
            uint32_t af[4][4], bf[2][4];
#pragma unroll
            for (int mt = 0; mt < 4; mt++)
                ldsm4(af[mt], ab + swzh(warp_m * 64 + mt * 16 + lrow, chunk));
#pragma unroll
            for (int pr = 0; pr < 2; pr++)
                ldsm4(bf[pr], bb + swzh(warp_n * 32 + pr * 16 + lrow, chunk));
#pragma unroll
            for (int mt = 0; mt < 4; mt++)
#pragma unroll
                for (int nt = 0; nt < 4; nt++) {
                    int pr = nt >> 1, hf = nt & 1;
                    mma16816(acc[mt][nt], af[mt], bf[pr][hf], bf[pr][2 + hf]);
                }
        }
    }

    const int erow = lane >> 2, ecol = (lane & 3) * 2;
#pragma unroll
    for (int mt = 0; mt < 4; mt++) {
#pragma unroll
        for (int nt = 0; nt < 4; nt++) {
            int mg = mrow0 + warp_m * 64 + mt * 16 + erow;
            int cg = nrow0 + warp_n * 32 + nt * 8 + ecol;
            if (mg < Mrows)
                *(__half2*)(C + (size_t)mg * Ncols + cg) =
                    __floats2half2_rn(acc[mt][nt][0], acc[mt][nt][1]);
            if (mg + 8 < Mrows)
                *(__half2*)(C + (size_t)(mg + 8) * Ncols + cg) =
                    __floats2half2_rn(acc[mt][nt][2], acc[mt][nt][3]);
        }
    }
}

// ---------------- kernel 3: gather-sum gates + LSTM cell -----------------------
// 4 rows/block, 1024 blocks, 512 thr: each (row, gate-octet) handled by TWO
// thread-halves -> half the dependent-load chain per thread.
__global__ __launch_bounds__(512, 2) void kernelB(
    const int* __restrict__ ab_ids, const int* __restrict__ mv_ids,
    const float* __restrict__ h0, const float* __restrict__ c0,
    float* __restrict__ h1_dup, float* __restrict__ c1_dup, int dup)
{
    __shared__ float h0_s[4][128];
    __shared__ int   ids_s[4][64];
    __shared__ float gs[2][4][520];
    const int tid = threadIdx.x;
    const int b0 = blockIdx.x * 4;
    const int q = tid & 63;            // gate octet
    const int rg = (tid >> 6) & 3;     // row 0..3
    const int half = tid >> 8;         // 0/1

    int nz = 0;
    {
        float v = h0[b0 * 128 + tid];
        h0_s[tid >> 7][tid & 127] = v;
        nz |= (v != 0.f);
    }
    if (tid < 4 * 12) ids_s[tid / 12][tid % 12] = ab_ids[b0 * 12 + tid];
    if (tid >= 64 && tid < 64 + 4 * 48) {
        int t = tid - 64;
        ids_s[t / 48][12 + t % 48] = mv_ids[b0 * 48 + t];
    }
    const int anyh = __syncthreads_or(nz);

    u64 acc[4];
    if (half == 0) {
        const ulonglong2* np = (const ulonglong2*)(g_Num + (size_t)(b0 + rg) * NGATE + q * 8);
        acc[0] = np[0].x; acc[1] = np[0].y; acc[2] = np[1].x; acc[3] = np[1].y;
#pragma unroll
        for (int s = 0; s < 12; s++) {
            const uint4 v = *(const uint4*)(g_Tab +
                ((size_t)(ids_s[rg][s] * 12 + s) << 9) + q * 8);
            addh8(acc, v);
        }
#pragma unroll
        for (int s = 0; s < 18; s++) {
            const uint4 v = *(const uint4*)(g_Tmv +
                ((size_t)(ids_s[rg][12 + s] * 48 + s) << 9) + q * 8);
            addh8(acc, v);
        }
    } else {
        acc[0] = acc[1] = acc[2] = acc[3] = 0ULL;
#pragma unroll
        for (int s = 18; s < 48; s++) {
            const uint4 v = *(const uint4*)(g_Tmv +
                ((size_t)(ids_s[rg][12 + s] * 48 + s) << 9) + q * 8);
            addh8(acc, v);
        }
    }
    if (anyh) {
        const int k0 = half * 64;
        for (int k = k0; k < k0 + 64; k++) {
            const ulonglong2* wp = (const ulonglong2*)(g_WhhT + k * NGATE + q * 8);
            const ulonglong2 w0 = wp[0], w1 = wp[1];
            float hv = h0_s[rg][k];
            u64 aa = pk2(hv, hv);
            ffma2(acc[0], aa, w0.x); ffma2(acc[1], aa, w0.y);
            ffma2(acc[2], aa, w1.x); ffma2(acc[3], aa, w1.y);
        }
    }
    {
        float x0, x1, x2, x3;
        upk2(acc[0], x0, x1); upk2(acc[1], x2, x3);
        *(float4*)&gs[half][rg][q * 8] = make_float4(x0, x1, x2, x3);
        upk2(acc[2], x0, x1); upk2(acc[3], x2, x3);
        *(float4*)&gs[half][rg][q * 8 + 4] = make_float4(x0, x1, x2, x3);
    }
    __syncthreads();

    {
        const int r = tid >> 7, h = tid & 127;
        float iv = gs[0][r][h]       + gs[1][r][h];
        float fv = gs[0][r][128 + h] + gs[1][r][128 + h];
        float gv = gs[0][r][256 + h] + gs[1][r][256 + h];
        float ov = gs[0][r][384 + h] + gs[1][r][384 + h];
        iv = fast_sigmoid(iv);
        fv = fast_sigmoid(fv);
        ov = fast_sigmoid(ov);
        gv = fast_tanh(gv);
        float c0v = c0[(b0 + r) * LHID + h];
        float c1v = fv * c0v + iv * gv;
        float h1v = ov * fast_tanh(c1v);
        g_c1[(b0 + r) * LHID + h] = c1v;
        g_h1[(b0 + r) * LHID + h] = h1v;
        if (dup) {
            c1_dup[(b0 + r) * LHID + h] = c1v;
            h1_dup[(b0 + r) * LHID + h] = h1v;
        }
    }
}

// ---------------- kernel 4: MLP head + masked softmax (32 rows/block) ----------
#define CROWS 32
__global__ __launch_bounds__(256) void kernelC(
    const float* __restrict__ W1, const float* __restrict__ b1,
    const float* __restrict__ W2, const float* __restrict__ b2,
    const float* __restrict__ Wa, const float* __restrict__ ba,
    const float* __restrict__ mask, float* __restrict__ outp)
{
    extern __shared__ float sm[];
    float* W1t = sm;                 // [128][64]
    float* W2t = W1t + 8192;         // [64][128]
    float* Was = W2t + 8192;         // [9][132]
    float* h1s = Was + 9 * 132;      // [32][132]
    float* t1s = h1s + 32 * 132;     // [32][68]
    float* fts = t1s + 32 * 68;      // [32][132]
    float* lgs = fts + 32 * 132;     // [32][12]
    float* b1s = lgs + 32 * 12;      // 64
    float* b2s = b1s + 64;           // 128
    float* bas = b2s + 128;          // 12
    const int tid = threadIdx.x;
    const int b0 = blockIdx.x * CROWS;

    for (int i = tid; i < 64 * 32; i += 256) {
        int j = i >> 5, kq = i & 31;
        float4 v = *(const float4*)(W1 + j * 128 + kq * 4);
        W1t[(kq * 4 + 0) * 64 + j] = v.x;
        W1t[(kq * 4 + 1) * 64 + j] = v.y;
        W1t[(kq * 4 + 2) * 64 + j] = v.z;
        W1t[(kq * 4 + 3) * 64 + j] = v.w;
    }
    for (int i = tid; i < 128 * 16; i += 256) {
        int kk = i >> 4, jq = i & 15;
        float4 v = *(const float4*)(W2 + kk * 64 + jq * 4);
        W2t[(jq * 4 + 0) * 128 + kk] = v.x;
        W2t[(jq * 4 + 1) * 128 + kk] = v.y;
        W2t[(jq * 4 + 2) * 128 + kk] = v.z;
        W2t[(jq * 4 + 3) * 128 + kk] = v.w;
    }
    for (int i = tid; i < 9 * 32; i += 256) {
        int a = i >> 5, kq = i & 31;
        *(float4*)&Was[a * 132 + kq * 4] = *(const float4*)(Wa + a * 128 + kq * 4);
    }
    for (int i = tid; i < 32 * 32; i += 256) {
        int r = i >> 5, kq = i & 31;
        *(float4*)&h1s[r * 132 + kq * 4] = *(const float4*)(g_h1 + (size_t)(b0 + r) * 128 + kq * 4);
    }
    if (tid < 64) b1s[tid] = b1[tid];
    if (tid >= 64 && tid < 192) b2s[tid - 64] = b2[tid - 64];
    if (tid >= 192 && tid < 201) bas[tid - 192] = ba[tid - 192];
    __syncthreads();

    {
        const int jq = tid & 15, rp = tid >> 4;
        const int j0 = jq * 4, r0 = rp * 2;
        float acc0[4], acc1[4];
#pragma unroll
        for (int q = 0; q < 4; q++) { acc0[q] = b1s[j0 + q]; acc1[q] = acc0[q]; }
        for (int k4 = 0; k4 < 128; k4 += 4) {
            float4 a0 = *(const float4*)&h1s[r0 * 132 + k4];
            float4 a1 = *(const float4*)&h1s[(r0 + 1) * 132 + k4];
            const float* a0p = (const float*)&a0;
            const float* a1p = (const float*)&a1;
#pragma unroll
            for (int t = 0; t < 4; t++) {
                float4 w = *(const float4*)&W1t[(k4 + t) * 64 + j0];
                float av0 = a0p[t], av1 = a1p[t];
                acc0[0] = fmaf(av0, w.x, acc0[0]); acc0[1] = fmaf(av0, w.y, acc0[1]);
                acc0[2] = fmaf(av0, w.z, acc0[2]); acc0[3] = fmaf(av0, w.w, acc0[3]);
                acc1[0] = fmaf(av1, w.x, acc1[0]); acc1[1] = fmaf(av1, w.y, acc1[1]);
                acc1[2] = fmaf(av1, w.z, acc1[2]); acc1[3] = fmaf(av1, w.w, acc1[3]);
            }
        }
        *(float4*)&t1s[r0 * 68 + j0] = make_float4(
            fmaxf(acc0[0], 0.f), fmaxf(acc0[1], 0.f), fmaxf(acc0[2], 0.f), fmaxf(acc0[3], 0.f));
        *(float4*)&t1s[(r0 + 1) * 68 + j0] = make_float4(
            fmaxf(acc1[0], 0.f), fmaxf(acc1[1], 0.f), fmaxf(acc1[2], 0.f), fmaxf(acc1[3], 0.f));
    }
    __syncthreads();

    {
        const int jo = tid & 15, rp = tid >> 4;
        const int kk0 = jo * 8, r0 = rp * 2;
        float acc0[8], acc1[8];
#pragma unroll
        for (int q = 0; q < 8; q++) { acc0[q] = b2s[kk0 + q]; acc1[q] = acc0[q]; }
        for (int j4 = 0; j4 < 64; j4 += 4) {
            float4 a0 = *(const float4*)&t1s[r0 * 68 + j4];
            float4 a1 = *(const float4*)&t1s[(r0 + 1) * 68 + j4];
            const float* a0p = (const float*)&a0;
            const float* a1p = (const float*)&a1;
#pragma unroll
            for (int t = 0; t < 4; t++) {
                float4 w0 = *(const float4*)&W2t[(j4 + t) * 128 + kk0];
                float4 w1 = *(const float4*)&W2t[(j4 + t) * 128 + kk0 + 4];
                float av0 = a0p[t], av1 = a1p[t];
                acc0[0] = fmaf(av0, w0.x, acc0[0]); acc0[1] = fmaf(av0, w0.y, acc0[1]);
                acc0[2] = fmaf(av0, w0.z, acc0[2]); acc0[3] = fmaf(av0, w0.w, acc0[3]);
                acc0[4] = fmaf(av0, w1.x, acc0[4]); acc0[5] = fmaf(av0, w1.y, acc0[5]);
                acc0[6] = fmaf(av0, w1.z, acc0[6]); acc0[7] = fmaf(av0, w1.w, acc0[7]);
                acc1[0] = fmaf(av1, w0.x, acc1[0]); acc1[1] = fmaf(av1, w0.y, acc1[1]);
                acc1[2] = fmaf(av1, w0.z, acc1[2]); acc1[3] = fmaf(av1, w0.w, acc1[3]);
                acc1[4] = fmaf(av1, w1.x, acc1[4]); acc1[5] = fmaf(av1, w1.y, acc1[5]);
                acc1[6] = fmaf(av1, w1.z, acc1[6]); acc1[7] = fmaf(av1, w1.w, acc1[7]);
            }
        }
        *(float4*)&fts[r0 * 132 + kk0] = make_float4(acc0[0], acc0[1], acc0[2], acc0[3]);
        *(float4*)&fts[r0 * 132 + kk0 + 4] = make_float4(acc0[4], acc0[5], acc0[6], acc0[7]);
        *(float4*)&fts[(r0 + 1) * 132 + kk0] = make_float4(acc1[0], acc1[1], acc1[2], acc1[3]);
        *(float4*)&fts[(r0 + 1) * 132 + kk0 + 4] = make_float4(acc1[4], acc1[5], acc1[6], acc1[7]);
    }
    __syncthreads();

    for (int idx = tid; idx < CROWS * 9; idx += 256) {
        int r = idx / 9, a = idx - r * 9;
        float s = bas[a];
        for (int k4 = 0; k4 < 128; k4 += 4) {
            float4 f = *(const float4*)&fts[r * 132 + k4];
            float4 w = *(const float4*)&Was[a * 132 + k4];
            s = fmaf(f.x, w.x, s); s = fmaf(f.y, w.y, s);
            s = fmaf(f.z, w.z, s); s = fmaf(f.w, w.w, s);
        }
        lgs[r * 12 + a] = s;
    }
    __syncthreads();

    if (tid < CROWS) {
        int b = b0 + tid;
        float mx = -1e30f;
        for (int a = 0; a < 9; a++) mx = fmaxf(mx, lgs[tid * 12 + a]);
        float e[9]; float se = 0.f;
        for (int a = 0; a < 9; a++) { e[a] = expf(lgs[tid * 12 + a] - mx); se += e[a]; }
        float pm[9]; float ms = 0.f;
        for (int a = 0; a < 9; a++) {
            float p = e[a] / se;
            pm[a] = p * mask[b * 9 + a];
            ms += pm[a];
        }
        for (int a = 0; a < 9; a++)
            outp[b * 9 + a] = (ms > 0.f) ? pm[a] / ms : e[a] / se;
    }
}

// ---------------- host ---------------------------------------------------------
extern "C" void kernel_launch(void* const* d_in, const int* in_sizes, int n_in,
                              void* d_out, int out_size)
{
    const int*   ab_ids    = (const int*)d_in[0];
    const int*   mv_ids    = (const int*)d_in[1];
    const float* numerical = (const float*)d_in[2];
    const float* mask      = (const float*)d_in[3];
    const float* h0        = (const float*)d_in[4];
    const float* c0        = (const float*)d_in[5];
    const float* ability_emb = (const float*)d_in[6];
    const float* move_emb  = (const float*)d_in[7];
    const float* num_W     = (const float*)d_in[8];
    const float* num_b     = (const float*)d_in[9];
    const float* Wih       = (const float*)d_in[10];
    const float* Whh       = (const float*)d_in[11];
    const float* bih       = (const float*)d_in[12];
    const float* bhh       = (const float*)d_in[13];
    const float* W1        = (const float*)d_in[14];
    const float* b1        = (const float*)d_in[15];
    const float* W2        = (const float*)d_in[16];
    const float* b2        = (const float*)d_in[17];
    const float* Wa        = (const float*)d_in[18];
    const float* ba        = (const float*)d_in[19];
    float* outp = (float*)d_out;

    __half *tab = nullptr, *tmv = nullptr;
    __half *amv = nullptr, *aab = nullptr, *bmv = nullptr, *bab = nullptr;
    cudaGetSymbolAddress((void**)&tab, g_Tab);
    cudaGetSymbolAddress((void**)&tmv, g_Tmv);
    cudaGetSymbolAddress((void**)&amv, g_Amv);
    cudaGetSymbolAddress((void**)&aab, g_Aab);
    cudaGetSymbolAddress((void**)&bmv, g_Bmv);
    cudaGetSymbolAddress((void**)&bab, g_Bab);

    const int smTC = 65536;   // max(TC: 64 KB, Num: 63.25 KB)
    const int smC = (8192 + 8192 + 9 * 132 + 32 * 132 + 32 * 68 + 32 * 132 +
                     32 * 12 + 64 + 128 + 12) * 4;   // ~115 KB
    cudaFuncSetAttribute(kernelTCNum, cudaFuncAttributeMaxDynamicSharedMemorySize, smTC);
    cudaFuncSetAttribute(kernelC, cudaFuncAttributeMaxDynamicSharedMemorySize, smC);

    const int full = (out_size >= BNUM * (9 + LHID + LHID));
    float* h1d = full ? (outp + BNUM * 9) : nullptr;
    float* c1d = full ? (outp + BNUM * 9 + BNUM * LHID) : nullptr;

    // 1: fused split + A2
    kernelSplitA2<<<SPLIT_BLOCKS + NGATE, 128>>>(
        move_emb, ability_emb, Wih, num_W, num_b, bih, bhh, Whh, amv, aab, bmv, bab);

    // 2: merged Num + table GEMM
    kernelTCNum<<<CTAS_NUM + CTAS_MV + CTAS_AB, 256, smTC>>>(
        amv, bmv, aab, bab, tmv, tab, numerical);

    // 3: gather-sum + LSTM (split-slot, 512 thr)
    kernelB<<<BNUM / 4, 512>>>(ab_ids, mv_ids, h0, c0, h1d, c1d, full);

    // 4: MLP head + softmax (register-tiled)
    kernelC<<<BNUM / CROWS, 256, smC>>>(W1, b1, W2, b2, Wa, ba, mask, outp);
}